// round 11
// baseline (speedup 1.0000x reference)
#include <cuda_runtime.h>
#include <cuda_bf16.h>
#include <cstdint>
#include <cstddef>

#define Bn    64
#define Tn    256
#define Dn    256
#define Hn    512
#define G4    2048
#define SMAXN 14336   // >= 64 * 223 max active steps

// ---------------- device-global scratch (static: no allocations allowed) ----
__device__ int      g_Stotal;
__device__ int      g_sb[SMAXN];          // step -> sample b
__device__ int      g_st[SMAXN];          // step -> timestep t
__device__ int      g_outb[SMAXN];        // step -> b if last step of sample, else -1
__device__ float    g_pre[(size_t)SMAXN * G4];   // W_ih@x + b_ih + b_hh, permuted rows
__device__ unsigned long long g_pub[2][Hn];  // packed {h_bits(lo), tag(hi)} atomic words
__device__ float    g_hall[Bn * Hn];      // h after each sample's segment
__device__ float    g_z1[Bn * 1024];
__device__ float    g_z2[Bn * 1024];

// ---------------- helpers ---------------------------------------------------
// ACCURATE activations (libm expf/tanhf, ~2 ulp). The recurrence is only
// marginally contractive; per-step activation error is the dominant seed of
// divergence from the fp32 reference. The old fast-math tanh form
// (1-e^{-2|x|})/(1+e^{-2|x|}) had ~2e-4 relative error near x~0 from
// cancellation — THE lead suspect for the round-3 2.2e-2 failure.
__device__ __forceinline__ float sigm_f(float x) {
    return 1.0f / (1.0f + expf(-x));
}
__device__ __forceinline__ float tanh_f(float x) {
    return tanhf(x);
}
// Scalar 64-bit RELAXED ATOMIC load/store: PTX guarantees single-copy
// atomicity for same-size scalar atomics -> tag and data can never tear.
__device__ __forceinline__ unsigned long long poll_word(const unsigned long long* p) {
    unsigned long long v;
    asm volatile("ld.relaxed.gpu.global.b64 %0, [%1];" : "=l"(v) : "l"(p) : "memory");
    return v;
}
__device__ __forceinline__ void pub_word(unsigned long long* p, unsigned long long v) {
    asm volatile("st.relaxed.gpu.global.b64 [%0], %1;" :: "l"(p), "l"(v) : "memory");
}
__device__ __forceinline__ unsigned long long pack_ht(float h, unsigned tag) {
    return (unsigned long long)__float_as_uint(h) | ((unsigned long long)tag << 32);
}

// Row permutation: permuted row R' = 4*unit + gate  <->  original row = gate*512 + unit
__device__ __forceinline__ int perm_row(int Rp) { return (Rp & 3) * Hn + (Rp >> 2); }

// ---------------- setup: step maps, zero state ------------------------------
__global__ void setup_kernel(const int* __restrict__ starts, const int* __restrict__ ends) {
    __shared__ int s_off[Bn + 1];
    int tid = threadIdx.x;
    if (tid == 0) {
        int acc = 0;
        for (int b = 0; b < Bn; b++) { s_off[b] = acc; acc += ends[b] - starts[b]; }
        s_off[Bn] = acc;
        g_Stotal = acc;
    }
    __syncthreads();
    // h0 = 0 published with tag 0 in slot 0; slot 1 also cleared (replay safety)
    for (int i = tid; i < Hn; i += blockDim.x) {
        g_pub[0][i] = 0ull;
        g_pub[1][i] = 0ull;
    }
    if (tid < Bn) {
        int b = tid, st = starts[b], off = s_off[b], len = s_off[b + 1] - off;
        for (int i = 0; i < len; i++) {
            g_sb[off + i]   = b;
            g_st[off + i]   = st + 1 + i;
            g_outb[off + i] = (i == len - 1) ? b : -1;
        }
    }
}

// ---------------- Phase A: pre[s][R'] = W_ih@x[b,t] + b_ih + b_hh -----------
// tile 128 steps x 128 gate-rows, K-chunks of 32, 256 threads, 8x8 microtile
__global__ void __launch_bounds__(256) pre_kernel(const float* __restrict__ x,
                                                  const float* __restrict__ Wih,
                                                  const float* __restrict__ bih,
                                                  const float* __restrict__ bhh) {
    __shared__ __align__(16) float sx[32][132];
    __shared__ __align__(16) float sw[32][132];
    __shared__ int sxb[128];

    int Stot = g_Stotal;
    int s0 = blockIdx.x * 128;
    if (s0 >= Stot) return;
    int j0 = blockIdx.y * 128;
    int tid = threadIdx.x;
    int tx = tid & 15, ty = tid >> 4;

    if (tid < 128) {
        int s = s0 + tid;
        sxb[tid] = (s < Stot) ? (g_sb[s] * Tn + g_st[s]) * Dn : 0;
    }

    float bj[8];
#pragma unroll
    for (int jj = 0; jj < 8; jj++) {
        int jc = tx * 4 + (jj & 3) + ((jj >= 4) ? 64 : 0);
        int r = perm_row(j0 + jc);
        bj[jj] = bih[r] + bhh[r];
    }

    float acc[8][8];
#pragma unroll
    for (int a = 0; a < 8; a++)
#pragma unroll
        for (int b = 0; b < 8; b++) acc[a][b] = 0.0f;

    __syncthreads();

    for (int kc = 0; kc < 8; kc++) {
        int k0 = kc * 32;
        for (int idx = tid; idx < 4096; idx += 256) {
            int kk = idx & 31, i = idx >> 5;
            sx[kk][i] = x[sxb[i] + k0 + kk];
            int r = perm_row(j0 + i);
            sw[kk][i] = Wih[r * Dn + k0 + kk];
        }
        __syncthreads();
#pragma unroll
        for (int k = 0; k < 32; k++) {
            float4 a0 = *(const float4*)&sx[k][ty * 4];
            float4 a1 = *(const float4*)&sx[k][64 + ty * 4];
            float4 b0 = *(const float4*)&sw[k][tx * 4];
            float4 b1 = *(const float4*)&sw[k][64 + tx * 4];
            float av[8] = {a0.x, a0.y, a0.z, a0.w, a1.x, a1.y, a1.z, a1.w};
            float bv[8] = {b0.x, b0.y, b0.z, b0.w, b1.x, b1.y, b1.z, b1.w};
#pragma unroll
            for (int ii = 0; ii < 8; ii++)
#pragma unroll
                for (int jj = 0; jj < 8; jj++)
                    acc[ii][jj] = fmaf(av[ii], bv[jj], acc[ii][jj]);
        }
        __syncthreads();
    }

#pragma unroll
    for (int ii = 0; ii < 8; ii++) {
        int i = ty * 4 + (ii & 3) + ((ii >= 4) ? 64 : 0);
        int s = s0 + i;
        if (s < Stot) {
            float* op = g_pre + (size_t)s * G4 + j0;
            float4 v0 = make_float4(acc[ii][0] + bj[0], acc[ii][1] + bj[1],
                                    acc[ii][2] + bj[2], acc[ii][3] + bj[3]);
            float4 v1 = make_float4(acc[ii][4] + bj[4], acc[ii][5] + bj[5],
                                    acc[ii][6] + bj[6], acc[ii][7] + bj[7]);
            *(float4*)(op + tx * 4) = v0;
            *(float4*)(op + 64 + tx * 4) = v1;
        }
    }
}

// ---------------- Phase B: persistent sequential LSTM chain -----------------
// 64 CTAs x 512 threads. CTA c owns hidden units [8c,8c+8) => 32 permuted rows
// [32c,32c+32). Warp w owns rows 32c+2w, 32c+2w+1; W_hh slice lives in registers.
// Sync: per-unit atomic 8B {h,tag} words, double-buffered by step parity.
// Thread tid polls unit tid's word for tag==s (data+flag in ONE L2 round trip),
// redistributes via smem, producers publish {h, s+1} to the other slot.
// Buffer-reuse proof: publishing tag s+2 into slot s&1 requires having observed
// tag s+1 from every CTA, and a CTA publishes s+1 only after it consumed slot
// s&1 into smem -> no producer can overwrite a slot before all consumers read it.
__global__ void __launch_bounds__(512, 1) lstm_kernel(const float* __restrict__ Whh) {
    __shared__ __align__(16) float s_h[Hn];
    __shared__ float s_g[32];

    int tid = threadIdx.x, w = tid >> 5, l = tid & 31, c = blockIdx.x;

    float wr[2][16];
#pragma unroll
    for (int row = 0; row < 2; row++) {
        int r = perm_row(c * 32 + 2 * w + row);
        const float4* wp = (const float4*)(Whh + (size_t)r * Hn);
#pragma unroll
        for (int q = 0; q < 4; q++) {
            float4 v = wp[l + 32 * q];
            wr[row][4 * q + 0] = v.x; wr[row][4 * q + 1] = v.y;
            wr[row][4 * q + 2] = v.z; wr[row][4 * q + 3] = v.w;
        }
    }
    float c_state = 0.0f;          // cell state for unit 8c+l (warp 0, l<8 only)
    int Stot = g_Stotal;
    const int cbase = c * 8;
    __syncthreads();

    for (int s = 0; s < Stot; s++) {
        int p = s & 1;
        float4 pre4 = make_float4(0.f, 0.f, 0.f, 0.f);
        int ob = -1;
        if (w == 0 && l < 8) {     // prefetch elementwise operands (sync-independent)
            pre4 = __ldcg((const float4*)(g_pre + (size_t)s * G4 + c * 32) + l);
            ob = __ldcg(&g_outb[s]);
        }
        // poll own unit's {h, tag} word until tag == s (atomic 8B: data rides along)
        {
            const unsigned long long* wp8 = &g_pub[p][tid];
            unsigned long long v = poll_word(wp8);
            while ((unsigned)(v >> 32) != (unsigned)s) v = poll_word(wp8);
            s_h[tid] = __uint_as_float((unsigned)v);
        }
        __syncthreads();

        const float4* hp = (const float4*)s_h;
        float4 h0 = hp[l];
        float4 h1 = hp[l + 32];
        float4 h2 = hp[l + 64];
        float4 h3 = hp[l + 96];
        float hv[16] = {h0.x, h0.y, h0.z, h0.w, h1.x, h1.y, h1.z, h1.w,
                        h2.x, h2.y, h2.z, h2.w, h3.x, h3.y, h3.z, h3.w};
        float a0 = 0.f, a1 = 0.f, b0 = 0.f, b1 = 0.f;
#pragma unroll
        for (int q = 0; q < 16; q += 2) {
            a0 = fmaf(wr[0][q],     hv[q],     a0);
            a1 = fmaf(wr[0][q + 1], hv[q + 1], a1);
            b0 = fmaf(wr[1][q],     hv[q],     b0);
            b1 = fmaf(wr[1][q + 1], hv[q + 1], b1);
        }
        float d0 = a0 + a1, d1 = b0 + b1;
#pragma unroll
        for (int off = 16; off; off >>= 1) {
            d0 += __shfl_xor_sync(0xffffffffu, d0, off);
            d1 += __shfl_xor_sync(0xffffffffu, d1, off);
        }
        if (l == 0) { s_g[2 * w] = d0; s_g[2 * w + 1] = d1; }
        __syncthreads();

        if (w == 0 && l < 8) {
            float gi = pre4.x + s_g[4 * l + 0];
            float gf = pre4.y + s_g[4 * l + 1];
            float gg = pre4.z + s_g[4 * l + 2];
            float go = pre4.w + s_g[4 * l + 3];
            float cn = sigm_f(gf) * c_state + sigm_f(gi) * tanh_f(gg);
            float hn = sigm_f(go) * tanh_f(cn);
            c_state = cn;
            pub_word(&g_pub[p ^ 1][cbase + l], pack_ht(hn, (unsigned)(s + 1)));
            if (ob >= 0) g_hall[(size_t)ob * Hn + cbase + l] = hn;
        }
    }
}

// ---------------- Phase C: MLP head -----------------------------------------
__device__ __forceinline__ void mlp_worker(const float* __restrict__ in,
                                           const float* __restrict__ W,
                                           const float* __restrict__ bias,
                                           float* __restrict__ out, int K, int O) {
    int gw = blockIdx.x * (blockDim.x >> 5) + (threadIdx.x >> 5);
    int l = threadIdx.x & 31;
    if (gw >= Bn * O) return;
    int b = gw / O, o = gw - b * O;
    const float* ip = in + (size_t)b * K;
    const float* wp = W + (size_t)o * K;
    float sum = 0.f;
    for (int k = l; k < K; k += 32) sum = fmaf(__ldg(ip + k), __ldg(wp + k), sum);
#pragma unroll
    for (int off = 16; off; off >>= 1) sum += __shfl_xor_sync(0xffffffffu, sum, off);
    if (l == 0) out[gw] = fmaxf(sum + bias[o], 0.0f);
}

__global__ void mlp1_kernel(const float* __restrict__ W, const float* __restrict__ b) {
    mlp_worker(g_hall, W, b, g_z1, Hn, 2 * Hn);
}
__global__ void mlp2_kernel(const float* __restrict__ W, const float* __restrict__ b) {
    mlp_worker(g_z1, W, b, g_z2, 2 * Hn, 2 * Hn);
}
__global__ void final_kernel(const float* __restrict__ W3, const float* __restrict__ b3,
                             float* __restrict__ out) {
    int b = blockIdx.x, l = threadIdx.x;
    const float* zp = g_z2 + (size_t)b * (2 * Hn);
    float sum = 0.f;
    for (int k = l; k < 2 * Hn; k += 32) sum = fmaf(zp[k], W3[k], sum);
#pragma unroll
    for (int off = 16; off; off >>= 1) sum += __shfl_xor_sync(0xffffffffu, sum, off);
    if (l == 0) out[b] = 1.0f / (1.0f + expf(-(sum + b3[0])));
}

// ---------------- entry -----------------------------------------------------
extern "C" void kernel_launch(void* const* d_in, const int* in_sizes, int n_in,
                              void* d_out, int out_size) {
    const float* x      = (const float*)d_in[0];
    const float* tv     = (const float*)d_in[1];
    const float* Wih    = (const float*)d_in[2];
    const float* Whh    = (const float*)d_in[3];
    const float* bih    = (const float*)d_in[4];
    const float* bhh    = (const float*)d_in[5];
    const float* W1     = (const float*)d_in[6];
    const float* b1     = (const float*)d_in[7];
    const float* W2     = (const float*)d_in[8];
    const float* b2     = (const float*)d_in[9];
    const float* W3     = (const float*)d_in[10];
    const float* b3     = (const float*)d_in[11];
    const int*   starts = (const int*)d_in[12];
    const int*   ends   = (const int*)d_in[13];
    float* out = (float*)d_out;

    setup_kernel<<<1, 256>>>(starts, ends);
    pre_kernel<<<dim3(SMAXN / 128, G4 / 128), 256>>>(x, Wih, bih, bhh);
    lstm_kernel<<<64, 512>>>(Whh);
    mlp1_kernel<<<(Bn * 2 * Hn) / 8, 256>>>(W1, b1);
    mlp2_kernel<<<(Bn * 2 * Hn) / 8, 256>>>(W2, b2);
    final_kernel<<<Bn, 32>>>(W3, b3, out);
    if (out_size >= 2 * Bn) {
        cudaMemcpyAsync(out + Bn, tv, Bn * sizeof(float), cudaMemcpyDeviceToDevice);
    }
}

// round 12
// speedup vs baseline: 1.0284x; 1.0284x over previous
#include <cuda_runtime.h>
#include <cuda_bf16.h>
#include <cstdint>
#include <cstddef>

#define Bn    64
#define Tn    256
#define Dn    256
#define Hn    512
#define G4    2048
#define SMAXN 14336   // >= 64 * 223 max active steps

// ---------------- device-global scratch (static: no allocations allowed) ----
__device__ int      g_Stotal;
__device__ int      g_sb[SMAXN];          // step -> sample b
__device__ int      g_st[SMAXN];          // step -> timestep t
__device__ int      g_outb[SMAXN];        // step -> b if last step of sample, else -1
__device__ float    g_pre[(size_t)SMAXN * G4];   // W_ih@x + b_ih + b_hh, permuted rows
__device__ unsigned long long g_pub[2][Hn];  // packed {h_bits(lo), tag(hi)} atomic words
__device__ float    g_hall[Bn * Hn];      // h after each sample's segment
__device__ float    g_z1[Bn * 1024];
__device__ float    g_z2[Bn * 1024];

// ---------------- helpers ---------------------------------------------------
// FAST activations in cancellation-free, ABSOLUTE-error-safe forms.
// Round-11 measurement: final rel_err == per-step seed (no amplification),
// and headroom is 7.3e-8 vs 1e-3. MUFU-based forms below have abs err ~2e-7
// -> predicted final ~1e-6. (The round-3 failure is attributed to publish
// tearing, fixed by the b64 atomic words; NOT to activation precision.)
__device__ __forceinline__ float sigm_f(float x) {
    return __fdividef(1.0f, 1.0f + __expf(-x));
}
__device__ __forceinline__ float tanh_f(float x) {
    // 1 - 2/(e^{2x}+1): no catastrophic cancellation in the dominant term;
    // saturates correctly (e->inf => 1, e->0 => -1).
    float e = __expf(2.0f * x);
    return 1.0f - __fdividef(2.0f, e + 1.0f);
}
// Scalar 64-bit RELAXED ATOMIC load/store: PTX guarantees single-copy
// atomicity for same-size scalar atomics -> tag and data can never tear.
__device__ __forceinline__ unsigned long long poll_word(const unsigned long long* p) {
    unsigned long long v;
    asm volatile("ld.relaxed.gpu.global.b64 %0, [%1];" : "=l"(v) : "l"(p) : "memory");
    return v;
}
__device__ __forceinline__ void pub_word(unsigned long long* p, unsigned long long v) {
    asm volatile("st.relaxed.gpu.global.b64 [%0], %1;" :: "l"(p), "l"(v) : "memory");
}
__device__ __forceinline__ unsigned long long pack_ht(float h, unsigned tag) {
    return (unsigned long long)__float_as_uint(h) | ((unsigned long long)tag << 32);
}

// Row permutation: permuted row R' = 4*unit + gate  <->  original row = gate*512 + unit
__device__ __forceinline__ int perm_row(int Rp) { return (Rp & 3) * Hn + (Rp >> 2); }

// ---------------- setup: step maps, zero state ------------------------------
__global__ void setup_kernel(const int* __restrict__ starts, const int* __restrict__ ends) {
    __shared__ int s_off[Bn + 1];
    int tid = threadIdx.x;
    if (tid == 0) {
        int acc = 0;
        for (int b = 0; b < Bn; b++) { s_off[b] = acc; acc += ends[b] - starts[b]; }
        s_off[Bn] = acc;
        g_Stotal = acc;
    }
    __syncthreads();
    // h0 = 0 published with tag 0 in slot 0; slot 1 also cleared (replay safety)
    for (int i = tid; i < Hn; i += blockDim.x) {
        g_pub[0][i] = 0ull;
        g_pub[1][i] = 0ull;
    }
    if (tid < Bn) {
        int b = tid, st = starts[b], off = s_off[b], len = s_off[b + 1] - off;
        for (int i = 0; i < len; i++) {
            g_sb[off + i]   = b;
            g_st[off + i]   = st + 1 + i;
            g_outb[off + i] = (i == len - 1) ? b : -1;
        }
    }
}

// ---------------- Phase A: pre[s][R'] = W_ih@x[b,t] + b_ih + b_hh -----------
// tile 128 steps x 128 gate-rows, K-chunks of 32, 256 threads, 8x8 microtile
__global__ void __launch_bounds__(256) pre_kernel(const float* __restrict__ x,
                                                  const float* __restrict__ Wih,
                                                  const float* __restrict__ bih,
                                                  const float* __restrict__ bhh) {
    __shared__ __align__(16) float sx[32][132];
    __shared__ __align__(16) float sw[32][132];
    __shared__ int sxb[128];

    int Stot = g_Stotal;
    int s0 = blockIdx.x * 128;
    if (s0 >= Stot) return;
    int j0 = blockIdx.y * 128;
    int tid = threadIdx.x;
    int tx = tid & 15, ty = tid >> 4;

    if (tid < 128) {
        int s = s0 + tid;
        sxb[tid] = (s < Stot) ? (g_sb[s] * Tn + g_st[s]) * Dn : 0;
    }

    float bj[8];
#pragma unroll
    for (int jj = 0; jj < 8; jj++) {
        int jc = tx * 4 + (jj & 3) + ((jj >= 4) ? 64 : 0);
        int r = perm_row(j0 + jc);
        bj[jj] = bih[r] + bhh[r];
    }

    float acc[8][8];
#pragma unroll
    for (int a = 0; a < 8; a++)
#pragma unroll
        for (int b = 0; b < 8; b++) acc[a][b] = 0.0f;

    __syncthreads();

    for (int kc = 0; kc < 8; kc++) {
        int k0 = kc * 32;
        for (int idx = tid; idx < 4096; idx += 256) {
            int kk = idx & 31, i = idx >> 5;
            sx[kk][i] = x[sxb[i] + k0 + kk];
            int r = perm_row(j0 + i);
            sw[kk][i] = Wih[r * Dn + k0 + kk];
        }
        __syncthreads();
#pragma unroll
        for (int k = 0; k < 32; k++) {
            float4 a0 = *(const float4*)&sx[k][ty * 4];
            float4 a1 = *(const float4*)&sx[k][64 + ty * 4];
            float4 b0 = *(const float4*)&sw[k][tx * 4];
            float4 b1 = *(const float4*)&sw[k][64 + tx * 4];
            float av[8] = {a0.x, a0.y, a0.z, a0.w, a1.x, a1.y, a1.z, a1.w};
            float bv[8] = {b0.x, b0.y, b0.z, b0.w, b1.x, b1.y, b1.z, b1.w};
#pragma unroll
            for (int ii = 0; ii < 8; ii++)
#pragma unroll
                for (int jj = 0; jj < 8; jj++)
                    acc[ii][jj] = fmaf(av[ii], bv[jj], acc[ii][jj]);
        }
        __syncthreads();
    }

#pragma unroll
    for (int ii = 0; ii < 8; ii++) {
        int i = ty * 4 + (ii & 3) + ((ii >= 4) ? 64 : 0);
        int s = s0 + i;
        if (s < Stot) {
            float* op = g_pre + (size_t)s * G4 + j0;
            float4 v0 = make_float4(acc[ii][0] + bj[0], acc[ii][1] + bj[1],
                                    acc[ii][2] + bj[2], acc[ii][3] + bj[3]);
            float4 v1 = make_float4(acc[ii][4] + bj[4], acc[ii][5] + bj[5],
                                    acc[ii][6] + bj[6], acc[ii][7] + bj[7]);
            *(float4*)(op + tx * 4) = v0;
            *(float4*)(op + 64 + tx * 4) = v1;
        }
    }
}

// ---------------- Phase B: persistent sequential LSTM chain -----------------
// 64 CTAs x 512 threads. CTA c owns hidden units [8c,8c+8) => 32 permuted rows
// [32c,32c+32). Warp w owns rows 32c+2w, 32c+2w+1; W_hh slice lives in registers.
// Sync: per-unit atomic 8B {h,tag} words, double-buffered by step parity.
// Elementwise tail: all 32 lanes of warp 0 each evaluate ONE gate activation
// in parallel (lane j: unit j>>2, gate j&3), shfl-regroup, lanes j%4==0 hold
// cell state and publish -> serial transcendental depth 2 instead of 5.
__global__ void __launch_bounds__(512, 1) lstm_kernel(const float* __restrict__ Whh) {
    __shared__ __align__(16) float s_h[Hn];
    __shared__ float s_g[32];

    int tid = threadIdx.x, w = tid >> 5, l = tid & 31, c = blockIdx.x;

    float wr[2][16];
#pragma unroll
    for (int row = 0; row < 2; row++) {
        int r = perm_row(c * 32 + 2 * w + row);
        const float4* wp = (const float4*)(Whh + (size_t)r * Hn);
#pragma unroll
        for (int q = 0; q < 4; q++) {
            float4 v = wp[l + 32 * q];
            wr[row][4 * q + 0] = v.x; wr[row][4 * q + 1] = v.y;
            wr[row][4 * q + 2] = v.z; wr[row][4 * q + 3] = v.w;
        }
    }
    float c_state = 0.0f;      // cell state for unit 8c + (l>>2), lanes l%4==0 of warp 0
    int Stot = g_Stotal;
    const int cbase = c * 8;
    __syncthreads();

    for (int s = 0; s < Stot; s++) {
        int p = s & 1;
        float pre_s = 0.0f;
        int ob = -1;
        if (w == 0) {          // prefetch elementwise operands (sync-independent)
            pre_s = __ldcg(g_pre + (size_t)s * G4 + c * 32 + l);  // one gate value/lane
            ob = __ldcg(&g_outb[s]);
        }
        // poll own unit's {h, tag} word until tag == s (atomic 8B: data rides along)
        {
            const unsigned long long* wp8 = &g_pub[p][tid];
            unsigned long long v = poll_word(wp8);
            while ((unsigned)(v >> 32) != (unsigned)s) v = poll_word(wp8);
            s_h[tid] = __uint_as_float((unsigned)v);
        }
        __syncthreads();

        const float4* hp = (const float4*)s_h;
        float4 h0 = hp[l];
        float4 h1 = hp[l + 32];
        float4 h2 = hp[l + 64];
        float4 h3 = hp[l + 96];
        float hv[16] = {h0.x, h0.y, h0.z, h0.w, h1.x, h1.y, h1.z, h1.w,
                        h2.x, h2.y, h2.z, h2.w, h3.x, h3.y, h3.z, h3.w};
        float a0 = 0.f, a1 = 0.f, b0 = 0.f, b1 = 0.f;
#pragma unroll
        for (int q = 0; q < 16; q += 2) {
            a0 = fmaf(wr[0][q],     hv[q],     a0);
            a1 = fmaf(wr[0][q + 1], hv[q + 1], a1);
            b0 = fmaf(wr[1][q],     hv[q],     b0);
            b1 = fmaf(wr[1][q + 1], hv[q + 1], b1);
        }
        float d0 = a0 + a1, d1 = b0 + b1;
#pragma unroll
        for (int off = 16; off; off >>= 1) {
            d0 += __shfl_xor_sync(0xffffffffu, d0, off);
            d1 += __shfl_xor_sync(0xffffffffu, d1, off);
        }
        if (l == 0) { s_g[2 * w] = d0; s_g[2 * w + 1] = d1; }
        __syncthreads();

        if (w == 0) {
            // lane j evaluates gate j&3 of unit j>>2 (gate 2 = g -> tanh)
            float gv = pre_s + s_g[l];
            float act = ((l & 3) == 2) ? tanh_f(gv) : sigm_f(gv);
            int base = l & ~3;
            float ai = __shfl_sync(0xffffffffu, act, base);
            float af = __shfl_sync(0xffffffffu, act, base + 1);
            float ag = __shfl_sync(0xffffffffu, act, base + 2);
            float ao = __shfl_sync(0xffffffffu, act, base + 3);
            if ((l & 3) == 0) {
                float cn = af * c_state + ai * ag;
                float hn = ao * tanh_f(cn);
                c_state = cn;
                int u = l >> 2;
                pub_word(&g_pub[p ^ 1][cbase + u], pack_ht(hn, (unsigned)(s + 1)));
                if (ob >= 0) g_hall[(size_t)ob * Hn + cbase + u] = hn;
            }
        }
    }
}

// ---------------- Phase C: MLP head -----------------------------------------
__device__ __forceinline__ void mlp_worker(const float* __restrict__ in,
                                           const float* __restrict__ W,
                                           const float* __restrict__ bias,
                                           float* __restrict__ out, int K, int O) {
    int gw = blockIdx.x * (blockDim.x >> 5) + (threadIdx.x >> 5);
    int l = threadIdx.x & 31;
    if (gw >= Bn * O) return;
    int b = gw / O, o = gw - b * O;
    const float* ip = in + (size_t)b * K;
    const float* wp = W + (size_t)o * K;
    float sum = 0.f;
    for (int k = l; k < K; k += 32) sum = fmaf(__ldg(ip + k), __ldg(wp + k), sum);
#pragma unroll
    for (int off = 16; off; off >>= 1) sum += __shfl_xor_sync(0xffffffffu, sum, off);
    if (l == 0) out[gw] = fmaxf(sum + bias[o], 0.0f);
}

__global__ void mlp1_kernel(const float* __restrict__ W, const float* __restrict__ b) {
    mlp_worker(g_hall, W, b, g_z1, Hn, 2 * Hn);
}
__global__ void mlp2_kernel(const float* __restrict__ W, const float* __restrict__ b) {
    mlp_worker(g_z1, W, b, g_z2, 2 * Hn, 2 * Hn);
}
__global__ void final_kernel(const float* __restrict__ W3, const float* __restrict__ b3,
                             float* __restrict__ out) {
    int b = blockIdx.x, l = threadIdx.x;
    const float* zp = g_z2 + (size_t)b * (2 * Hn);
    float sum = 0.f;
    for (int k = l; k < 2 * Hn; k += 32) sum = fmaf(zp[k], W3[k], sum);
#pragma unroll
    for (int off = 16; off; off >>= 1) sum += __shfl_xor_sync(0xffffffffu, sum, off);
    if (l == 0) out[b] = 1.0f / (1.0f + expf(-(sum + b3[0])));
}

// ---------------- entry -----------------------------------------------------
extern "C" void kernel_launch(void* const* d_in, const int* in_sizes, int n_in,
                              void* d_out, int out_size) {
    const float* x      = (const float*)d_in[0];
    const float* tv     = (const float*)d_in[1];
    const float* Wih    = (const float*)d_in[2];
    const float* Whh    = (const float*)d_in[3];
    const float* bih    = (const float*)d_in[4];
    const float* bhh    = (const float*)d_in[5];
    const float* W1     = (const float*)d_in[6];
    const float* b1     = (const float*)d_in[7];
    const float* W2     = (const float*)d_in[8];
    const float* b2     = (const float*)d_in[9];
    const float* W3     = (const float*)d_in[10];
    const float* b3     = (const float*)d_in[11];
    const int*   starts = (const int*)d_in[12];
    const int*   ends   = (const int*)d_in[13];
    float* out = (float*)d_out;

    setup_kernel<<<1, 256>>>(starts, ends);
    pre_kernel<<<dim3(SMAXN / 128, G4 / 128), 256>>>(x, Wih, bih, bhh);
    lstm_kernel<<<64, 512>>>(Whh);
    mlp1_kernel<<<(Bn * 2 * Hn) / 8, 256>>>(W1, b1);
    mlp2_kernel<<<(Bn * 2 * Hn) / 8, 256>>>(W2, b2);
    final_kernel<<<Bn, 32>>>(W3, b3, out);
    if (out_size >= 2 * Bn) {
        cudaMemcpyAsync(out + Bn, tv, Bn * sizeof(float), cudaMemcpyDeviceToDevice);
    }
}